// round 15
// baseline (speedup 1.0000x reference)
#include <cuda_runtime.h>
#include <math.h>
#include <stdint.h>

#define BB 2
#define TT 2048
#define DD 2048
#define HH 16
#define KVH 4
#define HD 128
#define RD 64

// ---------------- device scratch (no allocs allowed) ----------------
__device__ float g_qs[4096 * 2048];    // tf32-rounded scaled roped Q (row-major)
__device__ float g_att[4096 * 2048];   // attention out, A-perm tiles
__device__ float g_xr[4096 * 2048];    // tf32 x, A-perm tiles
__device__ float g_wqr[2048 * 2048];   // tf32 Wq, B-perm tiles
__device__ float g_wkr[2048 * 512];
__device__ float g_wvr[2048 * 512];
__device__ float g_wor[2048 * 2048];
__device__ float g_kr[2 * 4 * 2048 * 128];  // perm-tiled tf32 roped K
__device__ float g_vr[2 * 4 * 2048 * 128];  // perm-tiled tf32 V

__device__ __forceinline__ uint32_t f2tf(float x) {
    uint32_t r;
    asm("cvt.rna.tf32.f32 %0, %1;" : "=r"(r) : "f"(x));
    return r;
}
__device__ __forceinline__ float tfs(float x) {
    uint32_t r = f2tf(x);
    return __uint_as_float(r);
}
__device__ __forceinline__ uint32_t u(float x) { return __float_as_uint(x); }

// ---- flash K/V tile perms ----
__device__ __forceinline__ int kperm(int kvl, int d) {
    return (((d >> 4) << 2) + (kvl >> 3)) * 128
         + ((((kvl & 7) << 2) + (d & 3)) << 2)
         + (((d >> 3) & 1) << 1) + ((d >> 2) & 1);
}
__device__ __forceinline__ int vperm(int kvl, int d) {
    return (((kvl >> 3) << 3) + (d >> 4)) * 128
         + ((((d & 7) << 2) + (kvl & 3)) << 2)
         + (((d >> 3) & 1) << 1) + ((kvl >> 2) & 1);
}

// ---- GEMM operand perms: A tile 128m x 32k, B tile 32k x 128n ----
__device__ __forceinline__ int aperm(int mi, int ki) {
    return ((mi >> 4) * 4 + (ki >> 3)) * 128
         + (((mi & 7) << 2) + (ki & 3)) * 4
         + ((((ki & 7) >> 2) << 1) | ((mi >> 3) & 1));
}
__device__ __forceinline__ int bperm(int ki, int ni) {
    return ((ni >> 3) * 2 + (ki >> 4)) * 128
         + (((ni & 7) << 2) + (ki & 3)) * 4
         + ((ki >> 2) & 3);
}

#define MMA_TF32(d0,d1,d2,d3,a0,a1,a2,a3,b0,b1)                         \
    asm volatile(                                                        \
        "mma.sync.aligned.m16n8k8.row.col.f32.tf32.tf32.f32 "           \
        "{%0,%1,%2,%3}, {%4,%5,%6,%7}, {%8,%9}, {%0,%1,%2,%3};"         \
        : "+f"(d0), "+f"(d1), "+f"(d2), "+f"(d3)                         \
        : "r"(a0), "r"(a1), "r"(a2), "r"(a3), "r"(b0), "r"(b1))

#define CP_ASYNC16(smem_u32, gptr)                                       \
    asm volatile("cp.async.cg.shared.global [%0], [%1], 16;"             \
                 :: "r"(smem_u32), "l"(gptr))
#define CP_COMMIT() asm volatile("cp.async.commit_group;" ::: "memory")
#define CP_WAIT1()  asm volatile("cp.async.wait_group 1;"  ::: "memory")

// ------- tile-staged coalesced pre-round + permute ---------------------
__global__ __launch_bounds__(128) void preround_tiles(
    const float* __restrict__ x,  float* __restrict__ xr,
    const float* __restrict__ wq, float* __restrict__ wqr,
    const float* __restrict__ wk, float* __restrict__ wkr,
    const float* __restrict__ wv, float* __restrict__ wvr,
    const float* __restrict__ wo, float* __restrict__ wor) {
    __shared__ float sm[4096];
    int t = blockIdx.x, tid = threadIdx.x;

    if (t < 2048) {
        int mb = t >> 6, kb = t & 63;
        const float4* src = (const float4*)x;
        #pragma unroll
        for (int i = 0; i < 8; i++) {
            int c = tid + i * 128;
            int row = c >> 3, c4 = c & 7;
            float4 v = src[(size_t)(mb * 128 + row) * 512 + kb * 8 + c4];
            int ki = c4 * 4;
            sm[aperm(row, ki + 0)] = tfs(v.x);
            sm[aperm(row, ki + 1)] = tfs(v.y);
            sm[aperm(row, ki + 2)] = tfs(v.z);
            sm[aperm(row, ki + 3)] = tfs(v.w);
        }
        __syncthreads();
        float4* dst = (float4*)xr + (size_t)t * 1024;
        #pragma unroll
        for (int i = 0; i < 8; i++)
            dst[tid + i * 128] = ((const float4*)sm)[tid + i * 128];
    } else {
        const float* S; float* D; int N, tt;
        if (t < 3072)      { S = wq; D = wqr; N = 2048; tt = t - 2048; }
        else if (t < 3328) { S = wk; D = wkr; N = 512;  tt = t - 3072; }
        else if (t < 3584) { S = wv; D = wvr; N = 512;  tt = t - 3328; }
        else               { S = wo; D = wor; N = 2048; tt = t - 3584; }
        int nbt = N >> 7;
        int kb = tt / nbt, nb = tt % nbt;
        const float4* src = (const float4*)S;
        #pragma unroll
        for (int i = 0; i < 8; i++) {
            int c = tid + i * 128;
            int kr = c >> 5, n4 = c & 31;
            float4 v = src[(size_t)(kb * 32 + kr) * (N >> 2) + nb * 32 + n4];
            int ni = n4 * 4;
            sm[bperm(kr, ni + 0)] = tfs(v.x);
            sm[bperm(kr, ni + 1)] = tfs(v.y);
            sm[bperm(kr, ni + 2)] = tfs(v.z);
            sm[bperm(kr, ni + 3)] = tfs(v.w);
        }
        __syncthreads();
        float4* dst = (float4*)D + (size_t)tt * 1024;
        #pragma unroll
        for (int i = 0; i < 8; i++)
            dst[tid + i * 128] = ((const float4*)sm)[tid + i * 128];
    }
}

// ---------------- shared GEMM plumbing --------------------------------
#define STAGE_FLOATS 8192
#define GSMEM_BYTES (3 * STAGE_FLOATS * 4)
#define QSCALE 0.08838834764831845f

#define GEMM_MAINLOOP(NK)                                                 \
    issue(0, 0); CP_COMMIT();                                             \
    issue(1, 1); CP_COMMIT();                                             \
    for (int kt = 0; kt < (NK); kt++) {                                   \
        CP_WAIT1();                                                       \
        __syncthreads();                                                  \
        if (kt + 2 < (NK)) issue(kt + 2, (kt + 2) % 3);                   \
        CP_COMMIT();                                                      \
        const float4* As = (const float4*)(gsm + (kt % 3) * STAGE_FLOATS);\
        const float4* Bs = As + 1024;                                     \
        _Pragma("unroll")                                                 \
        for (int kp = 0; kp < 2; kp++) {                                  \
            float4 b4[4];                                                 \
            _Pragma("unroll")                                             \
            for (int nt = 0; nt < 4; nt++)                                \
                b4[nt] = Bs[((wn * 4 + nt) * 2 + kp) * 32 + lane];        \
            _Pragma("unroll")                                             \
            for (int s2 = 0; s2 < 2; s2++) {                              \
                float4 a4[4];                                             \
                _Pragma("unroll")                                         \
                for (int mt = 0; mt < 4; mt++)                            \
                    a4[mt] = As[((wm * 4 + mt) * 4 + kp * 2 + s2) * 32 + lane];\
                _Pragma("unroll")                                         \
                for (int mt = 0; mt < 4; mt++)                            \
                    _Pragma("unroll")                                     \
                    for (int nt = 0; nt < 4; nt++)                        \
                        MMA_TF32(acc[mt][nt][0], acc[mt][nt][1],          \
                                 acc[mt][nt][2], acc[mt][nt][3],          \
                                 u(a4[mt].x), u(a4[mt].y),                \
                                 u(a4[mt].z), u(a4[mt].w),                \
                                 s2 ? u(b4[nt].z) : u(b4[nt].x),          \
                                 s2 ? u(b4[nt].w) : u(b4[nt].y));         \
            }                                                             \
        }                                                                 \
    }

// -------- fused Q/K/V projection GEMM ----------------------------------
__global__ __launch_bounds__(256, 1) void gemm_qkv(
    const float* __restrict__ A,
    const float* __restrict__ Bq, const float* __restrict__ Bk,
    const float* __restrict__ Bv,
    float* __restrict__ Cq, float* __restrict__ Ck, float* __restrict__ Cv,
    float* __restrict__ C2k, float* __restrict__ C2v,
    const float* __restrict__ fcos, const float* __restrict__ fsin) {
    extern __shared__ float gsm[];
    uint32_t smem_u = (uint32_t)__cvta_generic_to_shared(gsm);

    int xb = blockIdx.x;
    int path, bcb, nbt;
    const float* B;
    if (xb < 16)      { path = 0; bcb = xb;      nbt = 16; B = Bq; }
    else if (xb < 20) { path = 1; bcb = xb - 16; nbt = 4;  B = Bk; }
    else              { path = 2; bcb = xb - 20; nbt = 4;  B = Bv; }

    int tid = threadIdx.x, lane = tid & 31;
    int w = tid >> 5, wm = w & 1, wn = w >> 1;
    int m0 = wm * 64, n0 = wn * 32;
    int g = lane >> 2, tig = lane & 3;
    int brow = blockIdx.y * 128, bcol = bcb * 128;

    float acc[4][4][4];
    #pragma unroll
    for (int mt = 0; mt < 4; mt++)
        #pragma unroll
        for (int nt = 0; nt < 4; nt++)
            #pragma unroll
            for (int i = 0; i < 4; i++) acc[mt][nt][i] = 0.f;

    auto issue = [&](int kt, int stage) {
        const float* atile = A + ((size_t)(brow >> 7) * (DD / 32) + kt) * 4096;
        const float* btile = B + ((size_t)kt * nbt + bcb) * 4096;
        uint32_t sa = smem_u + stage * STAGE_FLOATS * 4;
        uint32_t sb = sa + 4096 * 4;
        #pragma unroll
        for (int i = 0; i < 4; i++) {
            int c = tid + i * 256;
            CP_ASYNC16(sa + c * 16, atile + c * 4);
            CP_ASYNC16(sb + c * 16, btile + c * 4);
        }
    };

    GEMM_MAINLOOP(DD / 32)

    #pragma unroll
    for (int mt = 0; mt < 4; mt++) {
        int row = brow + m0 + mt * 16 + g;
        int row2 = row + 8;
        #pragma unroll
        for (int nt = 0; nt < 4; nt++) {
            int col = bcol + n0 + nt * 8 + tig * 2;
            float c0 = acc[mt][nt][0], c1 = acc[mt][nt][1];
            float c2 = acc[mt][nt][2], c3 = acc[mt][nt][3];

            int d = col & (HD - 1);
            if (path != 2 && d < RD) {
                int i = d >> 1;
                int t1 = row  & (TT - 1);
                int t2 = row2 & (TT - 1);
                float cc1 = fcos[t1 * (RD / 2) + i];
                float ss1 = fsin[t1 * (RD / 2) + i];
                float cc2 = fcos[t2 * (RD / 2) + i];
                float ss2 = fsin[t2 * (RD / 2) + i];
                float r0 = c0 * cc1 - c1 * ss1;
                float r1 = c0 * ss1 + c1 * cc1;
                float r2 = c2 * cc2 - c3 * ss2;
                float r3 = c2 * ss2 + c3 * cc2;
                c0 = r0; c1 = r1; c2 = r2; c3 = r3;
            }
            if (path == 0) {
                *(float2*)&Cq[(size_t)row  * (HH * HD) + col] =
                    make_float2(tfs(c0 * QSCALE), tfs(c1 * QSCALE));
                *(float2*)&Cq[(size_t)row2 * (HH * HD) + col] =
                    make_float2(tfs(c2 * QSCALE), tfs(c3 * QSCALE));
            } else {
                float* C  = (path == 1) ? Ck  : Cv;
                float* C2 = (path == 1) ? C2k : C2v;
                int kv = col >> 7;
                int b1i = row >> 11, t1 = row & (TT - 1);
                int b2i = row2 >> 11, t2 = row2 & (TT - 1);
                int bkv1 = b1i * KVH + kv, bkv2 = b2i * KVH + kv;
                size_t dst1 = ((size_t)bkv1 * TT + t1) * HD + d;
                size_t dst2 = ((size_t)bkv2 * TT + t2) * HD + d;
                *(float2*)&C[dst1] = make_float2(c0, c1);
                *(float2*)&C[dst2] = make_float2(c2, c3);
                size_t tb1 = ((size_t)bkv1 * (TT / 32) + (t1 >> 5)) * 4096;
                size_t tb2 = ((size_t)bkv2 * (TT / 32) + (t2 >> 5)) * 4096;
                int kvl1 = t1 & 31, kvl2 = t2 & 31;
                if (path == 1) {
                    C2[tb1 + kperm(kvl1, d)]     = tfs(c0);
                    C2[tb1 + kperm(kvl1, d + 1)] = tfs(c1);
                    C2[tb2 + kperm(kvl2, d)]     = tfs(c2);
                    C2[tb2 + kperm(kvl2, d + 1)] = tfs(c3);
                } else {
                    C2[tb1 + vperm(kvl1, d)]     = tfs(c0);
                    C2[tb1 + vperm(kvl1, d + 1)] = tfs(c1);
                    C2[tb2 + vperm(kvl2, d)]     = tfs(c2);
                    C2[tb2 + vperm(kvl2, d + 1)] = tfs(c3);
                }
            }
        }
    }
}

// -------- Wo projection GEMM (perm operands, plain output) -------------
__global__ __launch_bounds__(256, 1) void gemm_wo(
    const float* __restrict__ A, const float* __restrict__ B,
    float* __restrict__ C) {
    extern __shared__ float gsm[];
    uint32_t smem_u = (uint32_t)__cvta_generic_to_shared(gsm);
    const int N = DD;

    int tid = threadIdx.x, lane = tid & 31;
    int w = tid >> 5, wm = w & 1, wn = w >> 1;
    int m0 = wm * 64, n0 = wn * 32;
    int g = lane >> 2, tig = lane & 3;
    int brow = blockIdx.y * 128, bcol = blockIdx.x * 128;

    float acc[4][4][4];
    #pragma unroll
    for (int mt = 0; mt < 4; mt++)
        #pragma unroll
        for (int nt = 0; nt < 4; nt++)
            #pragma unroll
            for (int i = 0; i < 4; i++) acc[mt][nt][i] = 0.f;

    auto issue = [&](int kt, int stage) {
        const float* atile = A + ((size_t)(brow >> 7) * (DD / 32) + kt) * 4096;
        const float* btile = B + ((size_t)kt * (N >> 7) + (bcol >> 7)) * 4096;
        uint32_t sa = smem_u + stage * STAGE_FLOATS * 4;
        uint32_t sb = sa + 4096 * 4;
        #pragma unroll
        for (int i = 0; i < 4; i++) {
            int c = tid + i * 256;
            CP_ASYNC16(sa + c * 16, atile + c * 4);
            CP_ASYNC16(sb + c * 16, btile + c * 4);
        }
    };

    GEMM_MAINLOOP(DD / 32)

    #pragma unroll
    for (int mt = 0; mt < 4; mt++) {
        int row = brow + m0 + mt * 16 + g;
        int row2 = row + 8;
        #pragma unroll
        for (int nt = 0; nt < 4; nt++) {
            int col = bcol + n0 + nt * 8 + tig * 2;
            *(float2*)&C[(size_t)row  * N + col] =
                make_float2(acc[mt][nt][0], acc[mt][nt][1]);
            *(float2*)&C[(size_t)row2 * N + col] =
                make_float2(acc[mt][nt][2], acc[mt][nt][3]);
        }
    }
}

// ------ tensor-core causal flash attention (R12; perm K/V, A-perm out) -
#define FST 132
#define STAGE_F 8192
#define PS_OFF (2 * STAGE_F)
#define FSMEM_FLOATS (PS_OFF + 4 * 16 * 33)
#define FSMEM_BYTES (FSMEM_FLOATS * 4)

__global__ __launch_bounds__(128, 3) void flash_mma_kernel(
    const float* __restrict__ Q, const float* __restrict__ K,
    const float* __restrict__ V, float* __restrict__ O) {
    extern __shared__ float fsm[];
    uint32_t smem_u = (uint32_t)__cvta_generic_to_shared(fsm);

    int tid = threadIdx.x, lane = tid & 31, w = tid >> 5;
    int g = lane >> 2, tig = lane & 3;
    int b = blockIdx.z, h = blockIdx.y;
    int q0 = (gridDim.x - 1 - blockIdx.x) * 64;
    int kvh = h >> 2;

    size_t kvbase = (size_t)(b * KVH + kvh) * (TT / 32) * 4096;
    int ntiles = q0 / 32 + 2;

    {
        int r = tid >> 2, cb = (tid & 3) * 4;
        const float* qg = Q + ((size_t)(b * TT + q0 + r)) * (HH * HD) + h * HD;
        const float* qg2 = qg + (size_t)32 * (HH * HD);
        #pragma unroll
        for (int i = 0; i < 8; i++) {
            *(float4*)&fsm[r * FST + cb + i * 16] =
                *(const float4*)(qg + cb + i * 16);
            *(float4*)&fsm[(r + 32) * FST + cb + i * 16] =
                *(const float4*)(qg2 + cb + i * 16);
        }
    }
    __syncthreads();

    uint32_t qf[16][4];
    int qw = w * 16;
    #pragma unroll
    for (int kf = 0; kf < 16; kf++) {
        qf[kf][0] = u(fsm[(qw + g)     * FST + kf * 8 + tig]);
        qf[kf][1] = u(fsm[(qw + g + 8) * FST + kf * 8 + tig]);
        qf[kf][2] = u(fsm[(qw + g)     * FST + kf * 8 + tig + 4]);
        qf[kf][3] = u(fsm[(qw + g + 8) * FST + kf * 8 + tig + 4]);
    }
    __syncthreads();

    auto issue = [&](int tile, int stage) {
        const float* kb = K + kvbase + (size_t)tile * 4096;
        const float* vb = V + kvbase + (size_t)tile * 4096;
        uint32_t sk = smem_u + stage * STAGE_F * 4;
        uint32_t sv = sk + 4096 * 4;
        #pragma unroll
        for (int i = 0; i < 8; i++) {
            int c = tid + i * 128;
            CP_ASYNC16(sk + c * 16, kb + c * 4);
            CP_ASYNC16(sv + c * 16, vb + c * 4);
        }
    };

    issue(0, 0); CP_COMMIT();
    if (ntiles > 1) issue(1, 1);
    CP_COMMIT();

    float o[16][4];
    #pragma unroll
    for (int df = 0; df < 16; df++)
        o[df][0] = o[df][1] = o[df][2] = o[df][3] = 0.f;
    float m0 = -1e30f, m1 = -1e30f, l0 = 0.f, l1 = 0.f;

    int qglob = q0 + qw;
    float* Pw = fsm + PS_OFF + w * (16 * 33);

    for (int tile = 0; tile < ntiles; tile++) {
        int kv0 = tile * 32;
        const float* Ks = fsm + (tile & 1) * STAGE_F;
        const float* Vs = Ks + 4096;

        CP_WAIT1();
        __syncthreads();

        float s[4][4];
        #pragma unroll
        for (int nf = 0; nf < 4; nf++) {
            s[nf][0] = s[nf][1] = s[nf][2] = s[nf][3] = 0.f;
            #pragma unroll
            for (int kp = 0; kp < 8; kp++) {
                float4 bv = *(const float4*)&Ks[(kp * 4 + nf) * 128 + lane * 4];
                MMA_TF32(s[nf][0], s[nf][1], s[nf][2], s[nf][3],
                         qf[2 * kp][0], qf[2 * kp][1],
                         qf[2 * kp][2], qf[2 * kp][3],
                         u(bv.x), u(bv.y));
                MMA_TF32(s[nf][0], s[nf][1], s[nf][2], s[nf][3],
                         qf[2 * kp + 1][0], qf[2 * kp + 1][1],
                         qf[2 * kp + 1][2], qf[2 * kp + 1][3],
                         u(bv.z), u(bv.w));
            }
        }

        if (kv0 + 31 > qglob) {
            int r0 = qglob + g, r1 = qglob + g + 8;
            #pragma unroll
            for (int nf = 0; nf < 4; nf++) {
                int c = kv0 + nf * 8 + tig * 2;
                if (c     > r0) s[nf][0] = -1e30f;
                if (c + 1 > r0) s[nf][1] = -1e30f;
                if (c     > r1) s[nf][2] = -1e30f;
                if (c + 1 > r1) s[nf][3] = -1e30f;
            }
        }

        float mx0 = -1e30f, mx1 = -1e30f;
        #pragma unroll
        for (int nf = 0; nf < 4; nf++) {
            mx0 = fmaxf(mx0, fmaxf(s[nf][0], s[nf][1]));
            mx1 = fmaxf(mx1, fmaxf(s[nf][2], s[nf][3]));
        }
        mx0 = fmaxf(mx0, __shfl_xor_sync(0xffffffffu, mx0, 1));
        mx0 = fmaxf(mx0, __shfl_xor_sync(0xffffffffu, mx0, 2));
        mx1 = fmaxf(mx1, __shfl_xor_sync(0xffffffffu, mx1, 1));
        mx1 = fmaxf(mx1, __shfl_xor_sync(0xffffffffu, mx1, 2));
        float mn0 = fmaxf(m0, mx0), mn1 = fmaxf(m1, mx1);
        float sc0 = __expf(m0 - mn0), sc1 = __expf(m1 - mn1);
        m0 = mn0; m1 = mn1;

        float ps0 = 0.f, ps1 = 0.f;
        #pragma unroll
        for (int nf = 0; nf < 4; nf++) {
            float p0 = __expf(s[nf][0] - mn0);
            float p1 = __expf(s[nf][1] - mn0);
            float p2 = __expf(s[nf][2] - mn1);
            float p3 = __expf(s[nf][3] - mn1);
            ps0 += p0 + p1; ps1 += p2 + p3;
            Pw[(g    ) * 33 + nf * 8 + tig * 2    ] = tfs(p0);
            Pw[(g    ) * 33 + nf * 8 + tig * 2 + 1] = tfs(p1);
            Pw[(g + 8) * 33 + nf * 8 + tig * 2    ] = tfs(p2);
            Pw[(g + 8) * 33 + nf * 8 + tig * 2 + 1] = tfs(p3);
        }
        ps0 += __shfl_xor_sync(0xffffffffu, ps0, 1);
        ps0 += __shfl_xor_sync(0xffffffffu, ps0, 2);
        ps1 += __shfl_xor_sync(0xffffffffu, ps1, 1);
        ps1 += __shfl_xor_sync(0xffffffffu, ps1, 2);
        l0 = l0 * sc0 + ps0;
        l1 = l1 * sc1 + ps1;

        #pragma unroll
        for (int df = 0; df < 16; df++) {
            o[df][0] *= sc0; o[df][1] *= sc0;
            o[df][2] *= sc1; o[df][3] *= sc1;
        }
        __syncwarp();

        uint32_t pa[4][4];
        #pragma unroll
        for (int kf = 0; kf < 4; kf++) {
            pa[kf][0] = u(Pw[(g    ) * 33 + kf * 8 + tig]);
            pa[kf][1] = u(Pw[(g + 8) * 33 + kf * 8 + tig]);
            pa[kf][2] = u(Pw[(g    ) * 33 + kf * 8 + tig + 4]);
            pa[kf][3] = u(Pw[(g + 8) * 33 + kf * 8 + tig + 4]);
        }

        #pragma unroll
        for (int dfp = 0; dfp < 8; dfp++) {
            #pragma unroll
            for (int kf = 0; kf < 4; kf++) {
                float4 vv = *(const float4*)&Vs[(kf * 8 + dfp) * 128 + lane * 4];
                MMA_TF32(o[2 * dfp][0], o[2 * dfp][1],
                         o[2 * dfp][2], o[2 * dfp][3],
                         pa[kf][0], pa[kf][1], pa[kf][2], pa[kf][3],
                         u(vv.x), u(vv.y));
                MMA_TF32(o[2 * dfp + 1][0], o[2 * dfp + 1][1],
                         o[2 * dfp + 1][2], o[2 * dfp + 1][3],
                         pa[kf][0], pa[kf][1], pa[kf][2], pa[kf][3],
                         u(vv.z), u(vv.w));
            }
        }

        __syncthreads();
        if (tile + 2 < ntiles) issue(tile + 2, tile & 1);
        CP_COMMIT();
    }

    // epilogue: write tf32-rounded O into A-perm tiles for gemm_wo
    float inv0 = 1.f / l0, inv1 = 1.f / l1;
    auto aidx = [](int r, int c) -> size_t {
        int mi = r & 127, ki = c & 31;
        return ((size_t)(r >> 7) * (DD / 32) + (c >> 5)) * 4096
             + (size_t)aperm(mi, ki);
    };
    int r0g = b * TT + qglob + g;
    int r1g = r0g + 8;
    #pragma unroll
    for (int df = 0; df < 16; df++) {
        int c = h * HD + df * 8 + tig * 2;
        O[aidx(r0g, c)]     = tfs(o[df][0] * inv0);
        O[aidx(r0g, c + 1)] = tfs(o[df][1] * inv0);
        O[aidx(r1g, c)]     = tfs(o[df][2] * inv1);
        O[aidx(r1g, c + 1)] = tfs(o[df][3] * inv1);
    }
}

// ---------------- launch --------------------------------------------
extern "C" void kernel_launch(void* const* d_in, const int* in_sizes, int n_in,
                              void* d_out, int out_size) {
    const float* x    = (const float*)d_in[0];
    const float* fcos = (const float*)d_in[1];
    const float* fsin = (const float*)d_in[2];
    const float* Wq   = (const float*)d_in[3];
    const float* Wk   = (const float*)d_in[4];
    const float* Wv   = (const float*)d_in[5];
    const float* Wo   = (const float*)d_in[6];

    float* y    = (float*)d_out;
    float* outK = y + (size_t)BB * TT * DD;
    float* outV = outK + (size_t)BB * KVH * TT * HD;

    float *qs, *att, *xr, *wqr, *wkr, *wvr, *wor, *kr, *vr;
    cudaGetSymbolAddress((void**)&qs,  g_qs);
    cudaGetSymbolAddress((void**)&att, g_att);
    cudaGetSymbolAddress((void**)&xr,  g_xr);
    cudaGetSymbolAddress((void**)&wqr, g_wqr);
    cudaGetSymbolAddress((void**)&wkr, g_wkr);
    cudaGetSymbolAddress((void**)&wvr, g_wvr);
    cudaGetSymbolAddress((void**)&wor, g_wor);
    cudaGetSymbolAddress((void**)&kr,  g_kr);
    cudaGetSymbolAddress((void**)&vr,  g_vr);

    const int M = BB * TT;  // 4096
    static int smem_set = 0;
    if (!smem_set) {
        cudaFuncSetAttribute(flash_mma_kernel,
                             cudaFuncAttributeMaxDynamicSharedMemorySize, FSMEM_BYTES);
        cudaFuncSetAttribute(gemm_qkv,
                             cudaFuncAttributeMaxDynamicSharedMemorySize, GSMEM_BYTES);
        cudaFuncSetAttribute(gemm_wo,
                             cudaFuncAttributeMaxDynamicSharedMemorySize, GSMEM_BYTES);
        smem_set = 1;
    }

    preround_tiles<<<4608, 128>>>(x, xr, Wq, wqr, Wk, wkr, Wv, wvr, Wo, wor);

    gemm_qkv<<<dim3(24, M / 128), 256, GSMEM_BYTES>>>(
        xr, wqr, wkr, wvr, qs, outK, outV, kr, vr, fcos, fsin);

    flash_mma_kernel<<<dim3(TT / 64, HH, BB), 128, FSMEM_BYTES>>>(
        qs, kr, vr, att);

    gemm_wo<<<dim3(DD / 128, M / 128), 256, GSMEM_BYTES>>>(att, wor, y);
}

// round 16
// speedup vs baseline: 1.0883x; 1.0883x over previous
#include <cuda_runtime.h>
#include <math.h>
#include <stdint.h>

#define BB 2
#define TT 2048
#define DD 2048
#define HH 16
#define KVH 4
#define HD 128
#define RD 64

// ---------------- device scratch (no allocs allowed) ----------------
__device__ float g_qs[4096 * 2048];    // tf32-rounded scaled roped Q (row-major)
__device__ float g_att[4096 * 2048];   // attention out, A-perm tiles
__device__ float g_xr[4096 * 2048];    // tf32 x, A-perm tiles
__device__ float g_wqr[2048 * 2048];   // tf32 Wq, B-perm tiles
__device__ float g_wkr[2048 * 512];
__device__ float g_wvr[2048 * 512];
__device__ float g_wor[2048 * 2048];
__device__ float g_kr[2 * 4 * 2048 * 128];  // perm-tiled tf32 roped K
__device__ float g_vr[2 * 4 * 2048 * 128];  // perm-tiled tf32 V

__device__ __forceinline__ uint32_t f2tf(float x) {
    uint32_t r;
    asm("cvt.rna.tf32.f32 %0, %1;" : "=r"(r) : "f"(x));
    return r;
}
__device__ __forceinline__ float tfs(float x) {
    uint32_t r = f2tf(x);
    return __uint_as_float(r);
}
__device__ __forceinline__ uint32_t u(float x) { return __float_as_uint(x); }

// ---- flash K/V tile perms ----
__device__ __forceinline__ int kperm(int kvl, int d) {
    return (((d >> 4) << 2) + (kvl >> 3)) * 128
         + ((((kvl & 7) << 2) + (d & 3)) << 2)
         + (((d >> 3) & 1) << 1) + ((d >> 2) & 1);
}
__device__ __forceinline__ int vperm(int kvl, int d) {
    return (((kvl >> 3) << 3) + (d >> 4)) * 128
         + ((((d & 7) << 2) + (kvl & 3)) << 2)
         + (((d >> 3) & 1) << 1) + ((kvl >> 2) & 1);
}

// ---- GEMM operand perms: A tile 128m x 32k, B tile 32k x 128n ----
__device__ __forceinline__ int aperm(int mi, int ki) {
    return ((mi >> 4) * 4 + (ki >> 3)) * 128
         + (((mi & 7) << 2) + (ki & 3)) * 4
         + ((((ki & 7) >> 2) << 1) | ((mi >> 3) & 1));
}
__device__ __forceinline__ int bperm(int ki, int ni) {
    return ((ni >> 3) * 2 + (ki >> 4)) * 128
         + (((ni & 7) << 2) + (ki & 3)) * 4
         + ((ki >> 2) & 3);
}

#define MMA_TF32(d0,d1,d2,d3,a0,a1,a2,a3,b0,b1)                         \
    asm volatile(                                                        \
        "mma.sync.aligned.m16n8k8.row.col.f32.tf32.tf32.f32 "           \
        "{%0,%1,%2,%3}, {%4,%5,%6,%7}, {%8,%9}, {%0,%1,%2,%3};"         \
        : "+f"(d0), "+f"(d1), "+f"(d2), "+f"(d3)                         \
        : "r"(a0), "r"(a1), "r"(a2), "r"(a3), "r"(b0), "r"(b1))

#define CP_ASYNC16(smem_u32, gptr)                                       \
    asm volatile("cp.async.cg.shared.global [%0], [%1], 16;"             \
                 :: "r"(smem_u32), "l"(gptr))
#define CP_COMMIT() asm volatile("cp.async.commit_group;" ::: "memory")
#define CP_WAIT1()  asm volatile("cp.async.wait_group 1;"  ::: "memory")

// ------- tile-staged coalesced pre-round + permute ---------------------
__global__ __launch_bounds__(128) void preround_tiles(
    const float* __restrict__ x,  float* __restrict__ xr,
    const float* __restrict__ wq, float* __restrict__ wqr,
    const float* __restrict__ wk, float* __restrict__ wkr,
    const float* __restrict__ wv, float* __restrict__ wvr,
    const float* __restrict__ wo, float* __restrict__ wor) {
    __shared__ float sm[4096];
    int t = blockIdx.x, tid = threadIdx.x;

    if (t < 2048) {
        int mb = t >> 6, kb = t & 63;
        const float4* src = (const float4*)x;
        #pragma unroll
        for (int i = 0; i < 8; i++) {
            int c = tid + i * 128;
            int row = c >> 3, c4 = c & 7;
            float4 v = src[(size_t)(mb * 128 + row) * 512 + kb * 8 + c4];
            int ki = c4 * 4;
            sm[aperm(row, ki + 0)] = tfs(v.x);
            sm[aperm(row, ki + 1)] = tfs(v.y);
            sm[aperm(row, ki + 2)] = tfs(v.z);
            sm[aperm(row, ki + 3)] = tfs(v.w);
        }
        __syncthreads();
        float4* dst = (float4*)xr + (size_t)t * 1024;
        #pragma unroll
        for (int i = 0; i < 8; i++)
            dst[tid + i * 128] = ((const float4*)sm)[tid + i * 128];
    } else {
        const float* S; float* D; int N, tt;
        if (t < 3072)      { S = wq; D = wqr; N = 2048; tt = t - 2048; }
        else if (t < 3328) { S = wk; D = wkr; N = 512;  tt = t - 3072; }
        else if (t < 3584) { S = wv; D = wvr; N = 512;  tt = t - 3328; }
        else               { S = wo; D = wor; N = 2048; tt = t - 3584; }
        int nbt = N >> 7;
        int kb = tt / nbt, nb = tt % nbt;
        const float4* src = (const float4*)S;
        #pragma unroll
        for (int i = 0; i < 8; i++) {
            int c = tid + i * 128;
            int kr = c >> 5, n4 = c & 31;
            float4 v = src[(size_t)(kb * 32 + kr) * (N >> 2) + nb * 32 + n4];
            int ni = n4 * 4;
            sm[bperm(kr, ni + 0)] = tfs(v.x);
            sm[bperm(kr, ni + 1)] = tfs(v.y);
            sm[bperm(kr, ni + 2)] = tfs(v.z);
            sm[bperm(kr, ni + 3)] = tfs(v.w);
        }
        __syncthreads();
        float4* dst = (float4*)D + (size_t)tt * 1024;
        #pragma unroll
        for (int i = 0; i < 8; i++)
            dst[tid + i * 128] = ((const float4*)sm)[tid + i * 128];
    }
}

// ---------------- shared GEMM plumbing --------------------------------
#define STAGE_FLOATS 8192
#define GSMEM_BYTES (3 * STAGE_FLOATS * 4)
#define QSCALE 0.08838834764831845f

#define GEMM_MAINLOOP(NK)                                                 \
    issue(0, 0); CP_COMMIT();                                             \
    issue(1, 1); CP_COMMIT();                                             \
    for (int kt = 0; kt < (NK); kt++) {                                   \
        CP_WAIT1();                                                       \
        __syncthreads();                                                  \
        if (kt + 2 < (NK)) issue(kt + 2, (kt + 2) % 3);                   \
        CP_COMMIT();                                                      \
        const float4* As = (const float4*)(gsm + (kt % 3) * STAGE_FLOATS);\
        const float4* Bs = As + 1024;                                     \
        _Pragma("unroll")                                                 \
        for (int kp = 0; kp < 2; kp++) {                                  \
            float4 b4[4];                                                 \
            _Pragma("unroll")                                             \
            for (int nt = 0; nt < 4; nt++)                                \
                b4[nt] = Bs[((wn * 4 + nt) * 2 + kp) * 32 + lane];        \
            _Pragma("unroll")                                             \
            for (int s2 = 0; s2 < 2; s2++) {                              \
                float4 a4[4];                                             \
                _Pragma("unroll")                                         \
                for (int mt = 0; mt < 4; mt++)                            \
                    a4[mt] = As[((wm * 4 + mt) * 4 + kp * 2 + s2) * 32 + lane];\
                _Pragma("unroll")                                         \
                for (int mt = 0; mt < 4; mt++)                            \
                    _Pragma("unroll")                                     \
                    for (int nt = 0; nt < 4; nt++)                        \
                        MMA_TF32(acc[mt][nt][0], acc[mt][nt][1],          \
                                 acc[mt][nt][2], acc[mt][nt][3],          \
                                 u(a4[mt].x), u(a4[mt].y),                \
                                 u(a4[mt].z), u(a4[mt].w),                \
                                 s2 ? u(b4[nt].z) : u(b4[nt].x),          \
                                 s2 ? u(b4[nt].w) : u(b4[nt].y));         \
            }                                                             \
        }                                                                 \
    }

// -------- fused Q/K/V projection GEMM ----------------------------------
__global__ __launch_bounds__(256, 2) void gemm_qkv(
    const float* __restrict__ A,
    const float* __restrict__ Bq, const float* __restrict__ Bk,
    const float* __restrict__ Bv,
    float* __restrict__ Cq, float* __restrict__ Ck, float* __restrict__ Cv,
    float* __restrict__ C2k, float* __restrict__ C2v,
    const float* __restrict__ fcos, const float* __restrict__ fsin) {
    extern __shared__ float gsm[];
    uint32_t smem_u = (uint32_t)__cvta_generic_to_shared(gsm);

    int xb = blockIdx.x;
    int path, bcb, nbt;
    const float* B;
    if (xb < 16)      { path = 0; bcb = xb;      nbt = 16; B = Bq; }
    else if (xb < 20) { path = 1; bcb = xb - 16; nbt = 4;  B = Bk; }
    else              { path = 2; bcb = xb - 20; nbt = 4;  B = Bv; }

    int tid = threadIdx.x, lane = tid & 31;
    int w = tid >> 5, wm = w & 1, wn = w >> 1;
    int m0 = wm * 64, n0 = wn * 32;
    int g = lane >> 2, tig = lane & 3;
    int brow = blockIdx.y * 128, bcol = bcb * 128;

    float acc[4][4][4];
    #pragma unroll
    for (int mt = 0; mt < 4; mt++)
        #pragma unroll
        for (int nt = 0; nt < 4; nt++)
            #pragma unroll
            for (int i = 0; i < 4; i++) acc[mt][nt][i] = 0.f;

    auto issue = [&](int kt, int stage) {
        const float* atile = A + ((size_t)(brow >> 7) * (DD / 32) + kt) * 4096;
        const float* btile = B + ((size_t)kt * nbt + bcb) * 4096;
        uint32_t sa = smem_u + stage * STAGE_FLOATS * 4;
        uint32_t sb = sa + 4096 * 4;
        #pragma unroll
        for (int i = 0; i < 4; i++) {
            int c = tid + i * 256;
            CP_ASYNC16(sa + c * 16, atile + c * 4);
            CP_ASYNC16(sb + c * 16, btile + c * 4);
        }
    };

    GEMM_MAINLOOP(DD / 32)

    #pragma unroll
    for (int mt = 0; mt < 4; mt++) {
        int row = brow + m0 + mt * 16 + g;
        int row2 = row + 8;
        #pragma unroll
        for (int nt = 0; nt < 4; nt++) {
            int col = bcol + n0 + nt * 8 + tig * 2;
            float c0 = acc[mt][nt][0], c1 = acc[mt][nt][1];
            float c2 = acc[mt][nt][2], c3 = acc[mt][nt][3];

            int d = col & (HD - 1);
            if (path != 2 && d < RD) {
                int i = d >> 1;
                int t1 = row  & (TT - 1);
                int t2 = row2 & (TT - 1);
                float cc1 = fcos[t1 * (RD / 2) + i];
                float ss1 = fsin[t1 * (RD / 2) + i];
                float cc2 = fcos[t2 * (RD / 2) + i];
                float ss2 = fsin[t2 * (RD / 2) + i];
                float r0 = c0 * cc1 - c1 * ss1;
                float r1 = c0 * ss1 + c1 * cc1;
                float r2 = c2 * cc2 - c3 * ss2;
                float r3 = c2 * ss2 + c3 * cc2;
                c0 = r0; c1 = r1; c2 = r2; c3 = r3;
            }
            if (path == 0) {
                *(float2*)&Cq[(size_t)row  * (HH * HD) + col] =
                    make_float2(tfs(c0 * QSCALE), tfs(c1 * QSCALE));
                *(float2*)&Cq[(size_t)row2 * (HH * HD) + col] =
                    make_float2(tfs(c2 * QSCALE), tfs(c3 * QSCALE));
            } else {
                float* C  = (path == 1) ? Ck  : Cv;
                float* C2 = (path == 1) ? C2k : C2v;
                int kv = col >> 7;
                int b1i = row >> 11, t1 = row & (TT - 1);
                int b2i = row2 >> 11, t2 = row2 & (TT - 1);
                int bkv1 = b1i * KVH + kv, bkv2 = b2i * KVH + kv;
                size_t dst1 = ((size_t)bkv1 * TT + t1) * HD + d;
                size_t dst2 = ((size_t)bkv2 * TT + t2) * HD + d;
                *(float2*)&C[dst1] = make_float2(c0, c1);
                *(float2*)&C[dst2] = make_float2(c2, c3);
                size_t tb1 = ((size_t)bkv1 * (TT / 32) + (t1 >> 5)) * 4096;
                size_t tb2 = ((size_t)bkv2 * (TT / 32) + (t2 >> 5)) * 4096;
                int kvl1 = t1 & 31, kvl2 = t2 & 31;
                if (path == 1) {
                    C2[tb1 + kperm(kvl1, d)]     = tfs(c0);
                    C2[tb1 + kperm(kvl1, d + 1)] = tfs(c1);
                    C2[tb2 + kperm(kvl2, d)]     = tfs(c2);
                    C2[tb2 + kperm(kvl2, d + 1)] = tfs(c3);
                } else {
                    C2[tb1 + vperm(kvl1, d)]     = tfs(c0);
                    C2[tb1 + vperm(kvl1, d + 1)] = tfs(c1);
                    C2[tb2 + vperm(kvl2, d)]     = tfs(c2);
                    C2[tb2 + vperm(kvl2, d + 1)] = tfs(c3);
                }
            }
        }
    }
}

// -------- Wo projection GEMM (perm operands, plain output) -------------
__global__ __launch_bounds__(256, 2) void gemm_wo(
    const float* __restrict__ A, const float* __restrict__ B,
    float* __restrict__ C) {
    extern __shared__ float gsm[];
    uint32_t smem_u = (uint32_t)__cvta_generic_to_shared(gsm);
    const int N = DD;

    int tid = threadIdx.x, lane = tid & 31;
    int w = tid >> 5, wm = w & 1, wn = w >> 1;
    int m0 = wm * 64, n0 = wn * 32;
    int g = lane >> 2, tig = lane & 3;
    int brow = blockIdx.y * 128, bcol = blockIdx.x * 128;

    float acc[4][4][4];
    #pragma unroll
    for (int mt = 0; mt < 4; mt++)
        #pragma unroll
        for (int nt = 0; nt < 4; nt++)
            #pragma unroll
            for (int i = 0; i < 4; i++) acc[mt][nt][i] = 0.f;

    auto issue = [&](int kt, int stage) {
        const float* atile = A + ((size_t)(brow >> 7) * (DD / 32) + kt) * 4096;
        const float* btile = B + ((size_t)kt * (N >> 7) + (bcol >> 7)) * 4096;
        uint32_t sa = smem_u + stage * STAGE_FLOATS * 4;
        uint32_t sb = sa + 4096 * 4;
        #pragma unroll
        for (int i = 0; i < 4; i++) {
            int c = tid + i * 256;
            CP_ASYNC16(sa + c * 16, atile + c * 4);
            CP_ASYNC16(sb + c * 16, btile + c * 4);
        }
    };

    GEMM_MAINLOOP(DD / 32)

    #pragma unroll
    for (int mt = 0; mt < 4; mt++) {
        int row = brow + m0 + mt * 16 + g;
        int row2 = row + 8;
        #pragma unroll
        for (int nt = 0; nt < 4; nt++) {
            int col = bcol + n0 + nt * 8 + tig * 2;
            *(float2*)&C[(size_t)row  * N + col] =
                make_float2(acc[mt][nt][0], acc[mt][nt][1]);
            *(float2*)&C[(size_t)row2 * N + col] =
                make_float2(acc[mt][nt][2], acc[mt][nt][3]);
        }
    }
}

// ------ tensor-core causal flash attention (perm K/V; A-perm output) ---
#define FST 132
#define STAGE_F 8192
#define PS_OFF (2 * STAGE_F)
#define FSMEM_FLOATS (PS_OFF + 4 * 16 * 33)
#define FSMEM_BYTES (FSMEM_FLOATS * 4)

__global__ __launch_bounds__(128, 3) void flash_mma_kernel(
    const float* __restrict__ Q, const float* __restrict__ K,
    const float* __restrict__ V, float* __restrict__ O) {
    extern __shared__ float fsm[];
    uint32_t smem_u = (uint32_t)__cvta_generic_to_shared(fsm);

    int tid = threadIdx.x, lane = tid & 31, w = tid >> 5;
    int g = lane >> 2, tig = lane & 3;
    int b = blockIdx.z, h = blockIdx.y;
    int q0 = (gridDim.x - 1 - blockIdx.x) * 64;
    int kvh = h >> 2;

    size_t kvbase = (size_t)(b * KVH + kvh) * (TT / 32) * 4096;
    int ntiles = q0 / 32 + 2;

    {
        int r = tid >> 2, cb = (tid & 3) * 4;
        const float* qg = Q + ((size_t)(b * TT + q0 + r)) * (HH * HD) + h * HD;
        const float* qg2 = qg + (size_t)32 * (HH * HD);
        #pragma unroll
        for (int i = 0; i < 8; i++) {
            *(float4*)&fsm[r * FST + cb + i * 16] =
                *(const float4*)(qg + cb + i * 16);
            *(float4*)&fsm[(r + 32) * FST + cb + i * 16] =
                *(const float4*)(qg2 + cb + i * 16);
        }
    }
    __syncthreads();

    uint32_t qf[16][4];
    int qw = w * 16;
    #pragma unroll
    for (int kf = 0; kf < 16; kf++) {
        qf[kf][0] = u(fsm[(qw + g)     * FST + kf * 8 + tig]);
        qf[kf][1] = u(fsm[(qw + g + 8) * FST + kf * 8 + tig]);
        qf[kf][2] = u(fsm[(qw + g)     * FST + kf * 8 + tig + 4]);
        qf[kf][3] = u(fsm[(qw + g + 8) * FST + kf * 8 + tig + 4]);
    }
    __syncthreads();

    auto issue = [&](int tile, int stage) {
        const float* kb = K + kvbase + (size_t)tile * 4096;
        const float* vb = V + kvbase + (size_t)tile * 4096;
        uint32_t sk = smem_u + stage * STAGE_F * 4;
        uint32_t sv = sk + 4096 * 4;
        #pragma unroll
        for (int i = 0; i < 8; i++) {
            int c = tid + i * 128;
            CP_ASYNC16(sk + c * 16, kb + c * 4);
            CP_ASYNC16(sv + c * 16, vb + c * 4);
        }
    };

    issue(0, 0); CP_COMMIT();
    if (ntiles > 1) issue(1, 1);
    CP_COMMIT();

    float o[16][4];
    #pragma unroll
    for (int df = 0; df < 16; df++)
        o[df][0] = o[df][1] = o[df][2] = o[df][3] = 0.f;
    float m0 = -1e30f, m1 = -1e30f, l0 = 0.f, l1 = 0.f;

    int qglob = q0 + qw;
    float* Pw = fsm + PS_OFF + w * (16 * 33);

    for (int tile = 0; tile < ntiles; tile++) {
        int kv0 = tile * 32;
        const float* Ks = fsm + (tile & 1) * STAGE_F;
        const float* Vs = Ks + 4096;

        CP_WAIT1();
        __syncthreads();

        float s[4][4];
        #pragma unroll
        for (int nf = 0; nf < 4; nf++) {
            s[nf][0] = s[nf][1] = s[nf][2] = s[nf][3] = 0.f;
            #pragma unroll
            for (int kp = 0; kp < 8; kp++) {
                float4 bv = *(const float4*)&Ks[(kp * 4 + nf) * 128 + lane * 4];
                MMA_TF32(s[nf][0], s[nf][1], s[nf][2], s[nf][3],
                         qf[2 * kp][0], qf[2 * kp][1],
                         qf[2 * kp][2], qf[2 * kp][3],
                         u(bv.x), u(bv.y));
                MMA_TF32(s[nf][0], s[nf][1], s[nf][2], s[nf][3],
                         qf[2 * kp + 1][0], qf[2 * kp + 1][1],
                         qf[2 * kp + 1][2], qf[2 * kp + 1][3],
                         u(bv.z), u(bv.w));
            }
        }

        if (kv0 + 31 > qglob) {
            int r0 = qglob + g, r1 = qglob + g + 8;
            #pragma unroll
            for (int nf = 0; nf < 4; nf++) {
                int c = kv0 + nf * 8 + tig * 2;
                if (c     > r0) s[nf][0] = -1e30f;
                if (c + 1 > r0) s[nf][1] = -1e30f;
                if (c     > r1) s[nf][2] = -1e30f;
                if (c + 1 > r1) s[nf][3] = -1e30f;
            }
        }

        float mx0 = -1e30f, mx1 = -1e30f;
        #pragma unroll
        for (int nf = 0; nf < 4; nf++) {
            mx0 = fmaxf(mx0, fmaxf(s[nf][0], s[nf][1]));
            mx1 = fmaxf(mx1, fmaxf(s[nf][2], s[nf][3]));
        }
        mx0 = fmaxf(mx0, __shfl_xor_sync(0xffffffffu, mx0, 1));
        mx0 = fmaxf(mx0, __shfl_xor_sync(0xffffffffu, mx0, 2));
        mx1 = fmaxf(mx1, __shfl_xor_sync(0xffffffffu, mx1, 1));
        mx1 = fmaxf(mx1, __shfl_xor_sync(0xffffffffu, mx1, 2));
        float mn0 = fmaxf(m0, mx0), mn1 = fmaxf(m1, mx1);
        float sc0 = __expf(m0 - mn0), sc1 = __expf(m1 - mn1);
        m0 = mn0; m1 = mn1;

        float ps0 = 0.f, ps1 = 0.f;
        #pragma unroll
        for (int nf = 0; nf < 4; nf++) {
            float p0 = __expf(s[nf][0] - mn0);
            float p1 = __expf(s[nf][1] - mn0);
            float p2 = __expf(s[nf][2] - mn1);
            float p3 = __expf(s[nf][3] - mn1);
            ps0 += p0 + p1; ps1 += p2 + p3;
            Pw[(g    ) * 33 + nf * 8 + tig * 2    ] = tfs(p0);
            Pw[(g    ) * 33 + nf * 8 + tig * 2 + 1] = tfs(p1);
            Pw[(g + 8) * 33 + nf * 8 + tig * 2    ] = tfs(p2);
            Pw[(g + 8) * 33 + nf * 8 + tig * 2 + 1] = tfs(p3);
        }
        ps0 += __shfl_xor_sync(0xffffffffu, ps0, 1);
        ps0 += __shfl_xor_sync(0xffffffffu, ps0, 2);
        ps1 += __shfl_xor_sync(0xffffffffu, ps1, 1);
        ps1 += __shfl_xor_sync(0xffffffffu, ps1, 2);
        l0 = l0 * sc0 + ps0;
        l1 = l1 * sc1 + ps1;

        #pragma unroll
        for (int df = 0; df < 16; df++) {
            o[df][0] *= sc0; o[df][1] *= sc0;
            o[df][2] *= sc1; o[df][3] *= sc1;
        }
        __syncwarp();

        uint32_t pa[4][4];
        #pragma unroll
        for (int kf = 0; kf < 4; kf++) {
            pa[kf][0] = u(Pw[(g    ) * 33 + kf * 8 + tig]);
            pa[kf][1] = u(Pw[(g + 8) * 33 + kf * 8 + tig]);
            pa[kf][2] = u(Pw[(g    ) * 33 + kf * 8 + tig + 4]);
            pa[kf][3] = u(Pw[(g + 8) * 33 + kf * 8 + tig + 4]);
        }

        #pragma unroll
        for (int dfp = 0; dfp < 8; dfp++) {
            #pragma unroll
            for (int kf = 0; kf < 4; kf++) {
                float4 vv = *(const float4*)&Vs[(kf * 8 + dfp) * 128 + lane * 4];
                MMA_TF32(o[2 * dfp][0], o[2 * dfp][1],
                         o[2 * dfp][2], o[2 * dfp][3],
                         pa[kf][0], pa[kf][1], pa[kf][2], pa[kf][3],
                         u(vv.x), u(vv.y));
                MMA_TF32(o[2 * dfp + 1][0], o[2 * dfp + 1][1],
                         o[2 * dfp + 1][2], o[2 * dfp + 1][3],
                         pa[kf][0], pa[kf][1], pa[kf][2], pa[kf][3],
                         u(vv.z), u(vv.w));
            }
        }

        __syncthreads();
        if (tile + 2 < ntiles) issue(tile + 2, tile & 1);
        CP_COMMIT();
    }

    // epilogue: write tf32-rounded O into A-perm tiles for gemm_wo
    float inv0 = 1.f / l0, inv1 = 1.f / l1;
    auto aidx = [](int r, int c) -> size_t {
        int mi = r & 127, ki = c & 31;
        return ((size_t)(r >> 7) * (DD / 32) + (c >> 5)) * 4096
             + (size_t)aperm(mi, ki);
    };
    int r0g = b * TT + qglob + g;
    int r1g = r0g + 8;
    #pragma unroll
    for (int df = 0; df < 16; df++) {
        int c = h * HD + df * 8 + tig * 2;
        O[aidx(r0g, c)]     = tfs(o[df][0] * inv0);
        O[aidx(r0g, c + 1)] = tfs(o[df][1] * inv0);
        O[aidx(r1g, c)]     = tfs(o[df][2] * inv1);
        O[aidx(r1g, c + 1)] = tfs(o[df][3] * inv1);
    }
}

// ---------------- launch --------------------------------------------
extern "C" void kernel_launch(void* const* d_in, const int* in_sizes, int n_in,
                              void* d_out, int out_size) {
    const float* x    = (const float*)d_in[0];
    const float* fcos = (const float*)d_in[1];
    const float* fsin = (const float*)d_in[2];
    const float* Wq   = (const float*)d_in[3];
    const float* Wk   = (const float*)d_in[4];
    const float* Wv   = (const float*)d_in[5];
    const float* Wo   = (const float*)d_in[6];

    float* y    = (float*)d_out;
    float* outK = y + (size_t)BB * TT * DD;
    float* outV = outK + (size_t)BB * KVH * TT * HD;

    float *qs, *att, *xr, *wqr, *wkr, *wvr, *wor, *kr, *vr;
    cudaGetSymbolAddress((void**)&qs,  g_qs);
    cudaGetSymbolAddress((void**)&att, g_att);
    cudaGetSymbolAddress((void**)&xr,  g_xr);
    cudaGetSymbolAddress((void**)&wqr, g_wqr);
    cudaGetSymbolAddress((void**)&wkr, g_wkr);
    cudaGetSymbolAddress((void**)&wvr, g_wvr);
    cudaGetSymbolAddress((void**)&wor, g_wor);
    cudaGetSymbolAddress((void**)&kr,  g_kr);
    cudaGetSymbolAddress((void**)&vr,  g_vr);

    const int M = BB * TT;  // 4096
    static int smem_set = 0;
    if (!smem_set) {
        cudaFuncSetAttribute(flash_mma_kernel,
                             cudaFuncAttributeMaxDynamicSharedMemorySize, FSMEM_BYTES);
        cudaFuncSetAttribute(gemm_qkv,
                             cudaFuncAttributeMaxDynamicSharedMemorySize, GSMEM_BYTES);
        cudaFuncSetAttribute(gemm_wo,
                             cudaFuncAttributeMaxDynamicSharedMemorySize, GSMEM_BYTES);
        smem_set = 1;
    }

    preround_tiles<<<4608, 128>>>(x, xr, Wq, wqr, Wk, wkr, Wv, wvr, Wo, wor);

    gemm_qkv<<<dim3(24, M / 128), 256, GSMEM_BYTES>>>(
        xr, wqr, wkr, wvr, qs, outK, outV, kr, vr, fcos, fsin);

    flash_mma_kernel<<<dim3(TT / 64, HH, BB), 128, FSMEM_BYTES>>>(
        qs, kr, vr, att);

    gemm_wo<<<dim3(DD / 128, M / 128), 256, GSMEM_BYTES>>>(att, wor, y);
}